// round 1
// baseline (speedup 1.0000x reference)
#include <cuda_runtime.h>
#include <cstdint>

// QuantumKANRegressor: out[b] = sum_f sum_j kan[f,j] * T_j( tanh( sum_k w[f,k]*T_{k+1}(X[b,f]) / sum_k|w[f,k]| ) )
// B=65536, F=64, DEG=16 (T_1..T_16), KAN_DEG=5 (T_0..T_5)

typedef unsigned long long ull;

__device__ __forceinline__ ull pk2(float lo, float hi) {
    ull d; asm("mov.b64 %0, {%1, %2};" : "=l"(d) : "f"(lo), "f"(hi)); return d;
}
__device__ __forceinline__ void upk2(ull v, float& lo, float& hi) {
    asm("mov.b64 {%0, %1}, %2;" : "=f"(lo), "=f"(hi) : "l"(v));
}
__device__ __forceinline__ ull fma2(ull a, ull b, ull c) {
    ull d; asm("fma.rn.f32x2 %0, %1, %2, %3;" : "=l"(d) : "l"(a), "l"(b), "l"(c)); return d;
}
__device__ __forceinline__ ull add2(ull a, ull b) {
    ull d; asm("add.rn.f32x2 %0, %1, %2;" : "=l"(d) : "l"(a), "l"(b)); return d;
}
__device__ __forceinline__ ull mul2(ull a, ull b) {
    ull d; asm("mul.rn.f32x2 %0, %1, %2;" : "=l"(d) : "l"(a), "l"(b)); return d;
}
__device__ __forceinline__ float ex2f(float x) {
    float y; asm("ex2.approx.f32 %0, %1;" : "=f"(y) : "f"(x)); return y;
}
__device__ __forceinline__ float rcpf(float x) {
    float y; asm("rcp.approx.f32 %0, %1;" : "=f"(y) : "f"(x)); return y;
}
// accurate-enough tanh for |f|<=1: tanh(f) = 1 - 2/(1 + exp(2f)); exp via ex2
__device__ __forceinline__ float tanh_fast(float f) {
    float e = ex2f(f * 2.8853900817779268f);   // 2 * log2(e)
    float r = rcpf(e + 1.0f);
    return fmaf(-2.0f, r, 1.0f);
}

static constexpr int F    = 64;
static constexpr int DEG  = 16;
static constexpr int NBLK = 296;   // 2 blocks/SM * 148 SMs
static constexpr int NTHR = 256;

__global__ void __launch_bounds__(NTHR, 2)
qkan_kernel(const float* __restrict__ X,
            const float* __restrict__ W,    // [F, DEG]
            const float* __restrict__ KC,   // [1, F, 6]
            float* __restrict__ out,        // [B]
            int RP)                          // number of row-pairs = B/2
{
    const int lane = threadIdx.x & 31;
    const int gw   = (blockIdx.x * NTHR + threadIdx.x) >> 5;
    const int nW   = (gridDim.x * NTHR) >> 5;

    // ---------------- per-thread weight preprocessing (once) ----------------
    // Lane owns features f0 = 2*lane, f1 = 2*lane+1.
    // Sign-folded Chebyshev: X_k = s_k * T_k with s_k = -1 for k mod 4 in {2,3}.
    // Recurrence: X_{j} = fma( (j odd ? +2x : -2x), X_{j-1}, X_{j-2} )   (no negations)
    // Weight folded: w'_k = lcu[f][k-1] * s_k / denom[f].
    ull wq[2][DEG];   // packed (w', w') — same feature for both batch rows in the pair
    ull pc[2][6];     // packed KAN monomial (Horner) coefficients
    #pragma unroll
    for (int i = 0; i < 2; ++i) {
        const int f = 2 * lane + i;
        float t[DEG];
        float den = 0.0f;
        #pragma unroll
        for (int k = 0; k < DEG; ++k) { t[k] = W[f * DEG + k]; den += fabsf(t[k]); }
        const float rd = 1.0f / den;
        #pragma unroll
        for (int k = 0; k < DEG; ++k) {
            const int kk = k + 1;                 // Chebyshev order
            float v = t[k] * rd;
            if (kk & 2) v = -v;                   // s_k = -1 for kk mod 4 in {2,3}
            wq[i][k] = pk2(v, v);
        }
        // KAN Chebyshev (deg 5) -> monomial (stable at this degree):
        // T0=1, T1=z, T2=2z^2-1, T3=4z^3-3z, T4=8z^4-8z^2+1, T5=16z^5-20z^3+5z
        const float k0 = KC[f*6+0], k1 = KC[f*6+1], k2 = KC[f*6+2];
        const float k3 = KC[f*6+3], k4 = KC[f*6+4], k5 = KC[f*6+5];
        const float p0 = k0 - k2 + k4;
        const float p1 = k1 - 3.0f*k3 + 5.0f*k5;
        const float p2 = 2.0f*k2 - 8.0f*k4;
        const float p3 = 4.0f*k3 - 20.0f*k5;
        const float p4 = 8.0f*k4;
        const float p5 = 16.0f*k5;
        pc[i][0] = pk2(p0, p0); pc[i][1] = pk2(p1, p1); pc[i][2] = pk2(p2, p2);
        pc[i][3] = pk2(p3, p3); pc[i][4] = pk2(p4, p4); pc[i][5] = pk2(p5, p5);
    }

    const ull ONE2  = 0x3F8000003F800000ull;   // (1.0f, 1.0f)
    const ull NEG22 = 0xC0000000C0000000ull;   // (-2.0f, -2.0f)

    // ---------------- main loop: one warp = one row-pair per iteration ----------------
    for (int rp = gw; rp < RP; rp += nW) {
        const float2* r0 = (const float2*)(X + (size_t)(2 * rp)     * F);
        const float2* r1 = (const float2*)(X + (size_t)(2 * rp + 1) * F);
        const float2 a = __ldg(r0 + lane);   // features (f0, f1) of row 2*rp
        const float2 b = __ldg(r1 + lane);   // features (f0, f1) of row 2*rp+1

        ull acc = 0ull;                      // packed (0.0f, 0.0f)
        #pragma unroll
        for (int i = 0; i < 2; ++i) {
            const ull x   = (i == 0) ? pk2(a.x, b.x) : pk2(a.y, b.y);
            const ull p2x = add2(x, x);            // +2x
            const ull m2x = mul2(x, NEG22);        // -2x
            ull Xa = x;                            // X_1 = T_1
            ull Xb = fma2(m2x, x, ONE2);           // X_2 = 1 - 2x^2 = s_2 T_2
            ull feat = mul2(wq[i][0], Xa);
            feat = fma2(wq[i][1], Xb, feat);
            #pragma unroll
            for (int j = 3; j <= DEG; ++j) {
                const ull Xc = fma2((j & 1) ? p2x : m2x, Xb, Xa);
                feat = fma2(wq[i][j - 1], Xc, feat);
                Xa = Xb; Xb = Xc;
            }
            // tanh on each half (scalar MUFU path)
            float flo, fhi; upk2(feat, flo, fhi);
            const ull z = pk2(tanh_fast(flo), tanh_fast(fhi));
            // KAN deg-5 Horner
            ull r = pc[i][5];
            r = fma2(r, z, pc[i][4]);
            r = fma2(r, z, pc[i][3]);
            r = fma2(r, z, pc[i][2]);
            r = fma2(r, z, pc[i][1]);
            r = fma2(r, z, pc[i][0]);
            acc = add2(acc, r);
        }

        // warp reduction over 64 features (both rows ride in the packed halves)
        #pragma unroll
        for (int o = 16; o; o >>= 1)
            acc = add2(acc, __shfl_xor_sync(0xffffffffu, acc, o));

        if (lane == 0) {
            float lo, hi; upk2(acc, lo, hi);
            out[2 * rp]     = lo;
            out[2 * rp + 1] = hi;
        }
    }
}

extern "C" void kernel_launch(void* const* d_in, const int* in_sizes, int n_in,
                              void* d_out, int out_size)
{
    const float* X  = (const float*)d_in[0];   // [B, 64] fp32
    const float* W  = (const float*)d_in[1];   // [64, 16] fp32
    const float* KC = (const float*)d_in[2];   // [1, 64, 6] fp32
    float* out = (float*)d_out;                // [B] fp32

    const int B  = in_sizes[0] / F;            // 65536
    const int RP = B / 2;

    qkan_kernel<<<NBLK, NTHR>>>(X, W, KC, out, RP);
}

// round 2
// speedup vs baseline: 1.3259x; 1.3259x over previous
#include <cuda_runtime.h>
#include <cstdint>

// QuantumKANRegressor: out[b] = sum_f sum_j kan[f,j] * T_j( tanh( sum_k w[f,k]*T_{k+1}(X[b,f]) / sum_k|w[f,k]| ) )
// B=65536, F=64, DEG=16 (T_1..T_16), KAN_DEG=5 (T_0..T_5)
//
// R2: weights in SMEM (parity-plane layout, conflict-free LDS), 4 row-pairs
// (8 rows) in flight per warp-iteration for ILP; packed f32x2 math throughout.

typedef unsigned long long ull;

__device__ __forceinline__ ull pk2(float lo, float hi) {
    ull d; asm("mov.b64 %0, {%1, %2};" : "=l"(d) : "f"(lo), "f"(hi)); return d;
}
__device__ __forceinline__ void upk2(ull v, float& lo, float& hi) {
    asm("mov.b64 {%0, %1}, %2;" : "=f"(lo), "=f"(hi) : "l"(v));
}
__device__ __forceinline__ ull fma2(ull a, ull b, ull c) {
    ull d; asm("fma.rn.f32x2 %0, %1, %2, %3;" : "=l"(d) : "l"(a), "l"(b), "l"(c)); return d;
}
__device__ __forceinline__ ull add2(ull a, ull b) {
    ull d; asm("add.rn.f32x2 %0, %1, %2;" : "=l"(d) : "l"(a), "l"(b)); return d;
}
__device__ __forceinline__ ull mul2(ull a, ull b) {
    ull d; asm("mul.rn.f32x2 %0, %1, %2;" : "=l"(d) : "l"(a), "l"(b)); return d;
}
__device__ __forceinline__ float ex2f(float x) {
    float y; asm("ex2.approx.f32 %0, %1;" : "=f"(y) : "f"(x)); return y;
}
__device__ __forceinline__ float rcpf(float x) {
    float y; asm("rcp.approx.f32 %0, %1;" : "=f"(y) : "f"(x)); return y;
}
// tanh(f) = 1 - 2/(1 + exp(2f)); exp via ex2 (MUFU pipe, off the FMA pipe)
__device__ __forceinline__ float tanh_fast(float f) {
    float e = ex2f(f * 2.8853900817779268f);   // 2 * log2(e)
    float r = rcpf(e + 1.0f);
    return fmaf(-2.0f, r, 1.0f);
}

static constexpr int F    = 64;
static constexpr int DEG  = 16;
static constexpr int NBLK = 296;   // 2 CTAs/SM * 148 SMs
static constexpr int NTHR = 256;
static constexpr int RPI  = 4;     // row-pairs per warp-iteration (8 rows)

__global__ void __launch_bounds__(NTHR, 2)
qkan_kernel(const float* __restrict__ X,
            const float* __restrict__ W,    // [F, DEG]
            const float* __restrict__ KC,   // [1, F, 6]
            float* __restrict__ out,        // [B]
            int RP)                          // number of row-pairs = B/2
{
    // Parity-plane weight storage: plane i holds features f = 2*l + i at slot l.
    // Lane reads plane[i][j][lane] -> consecutive 8B addresses across lanes:
    // conflict-free LDS.64.
    __shared__ ull wq_s[2][DEG][32];
    __shared__ ull pc_s[2][6][32];

    const int tid = threadIdx.x;

    // -------- per-block weight preprocessing (64 threads, once) --------
    if (tid < F) {
        const int f = tid;
        const int ip = f & 1;
        const int l  = f >> 1;
        float t[DEG];
        float den = 0.0f;
        #pragma unroll
        for (int k = 0; k < DEG; ++k) { t[k] = W[f * DEG + k]; den += fabsf(t[k]); }
        const float rd = 1.0f / den;
        // Sign-folded Chebyshev: X_k = s_k*T_k, s_k = -1 for k mod 4 in {2,3};
        // recurrence X_j = fma( (j odd ? +2x : -2x), X_{j-1}, X_{j-2} ).
        #pragma unroll
        for (int k = 0; k < DEG; ++k) {
            const int kk = k + 1;
            float v = t[k] * rd;
            if (kk & 2) v = -v;
            wq_s[ip][k][l] = pk2(v, v);
        }
        // KAN Chebyshev (deg 5) -> monomial Horner coefficients
        const float k0 = KC[f*6+0], k1 = KC[f*6+1], k2 = KC[f*6+2];
        const float k3 = KC[f*6+3], k4 = KC[f*6+4], k5 = KC[f*6+5];
        const float p0 = k0 - k2 + k4;
        const float p1 = k1 - 3.0f*k3 + 5.0f*k5;
        const float p2 = 2.0f*k2 - 8.0f*k4;
        const float p3 = 4.0f*k3 - 20.0f*k5;
        const float p4 = 8.0f*k4;
        const float p5 = 16.0f*k5;
        pc_s[ip][0][l] = pk2(p0, p0); pc_s[ip][1][l] = pk2(p1, p1);
        pc_s[ip][2][l] = pk2(p2, p2); pc_s[ip][3][l] = pk2(p3, p3);
        pc_s[ip][4][l] = pk2(p4, p4); pc_s[ip][5][l] = pk2(p5, p5);
    }
    __syncthreads();

    const ull ONE2  = 0x3F8000003F800000ull;   // (1.0f, 1.0f)
    const ull NEG22 = 0xC0000000C0000000ull;   // (-2.0f, -2.0f)

    const int lane = tid & 31;
    const int gw   = (blockIdx.x * NTHR + tid) >> 5;
    const int nW   = (gridDim.x * NTHR) >> 5;
    const int nG   = (RP + RPI - 1) / RPI;     // groups of RPI row-pairs

    for (int g = gw; g < nG; g += nW) {
        // rows 8g .. 8g+7 ; lane reads float2 (features 2*lane, 2*lane+1)
        const float2* base = (const float2*)X + (size_t)(8 * g) * 32 + lane;
        float2 a[RPI], b[RPI];
        #pragma unroll
        for (int r = 0; r < RPI; ++r) {
            const bool ok = (RPI * g + r) < RP;
            a[r] = ok ? __ldg(base + (2 * r)     * 32) : make_float2(0.f, 0.f);
            b[r] = ok ? __ldg(base + (2 * r + 1) * 32) : make_float2(0.f, 0.f);
        }

        ull acc[RPI];
        #pragma unroll
        for (int r = 0; r < RPI; ++r) acc[r] = 0ull;

        #pragma unroll
        for (int i = 0; i < 2; ++i) {       // feature-parity phase
            ull x[RPI], p2x[RPI], m2x[RPI], Xa[RPI], Xb[RPI], feat[RPI];
            #pragma unroll
            for (int r = 0; r < RPI; ++r) {
                const float xa = i ? a[r].y : a[r].x;
                const float xb = i ? b[r].y : b[r].x;
                x[r]   = pk2(xa, xb);
                p2x[r] = add2(x[r], x[r]);        // +2x
                m2x[r] = mul2(x[r], NEG22);       // -2x
                Xa[r]  = x[r];                    // X_1
                Xb[r]  = fma2(m2x[r], x[r], ONE2);// X_2 = 1 - 2x^2
            }
            {
                const ull w0 = wq_s[i][0][lane];
                const ull w1 = wq_s[i][1][lane];
                #pragma unroll
                for (int r = 0; r < RPI; ++r) {
                    feat[r] = mul2(w0, Xa[r]);
                    feat[r] = fma2(w1, Xb[r], feat[r]);
                }
            }
            #pragma unroll
            for (int j = 3; j <= DEG; ++j) {
                const ull w = wq_s[i][j - 1][lane];
                #pragma unroll
                for (int r = 0; r < RPI; ++r) {
                    const ull Xc = fma2((j & 1) ? p2x[r] : m2x[r], Xb[r], Xa[r]);
                    feat[r] = fma2(w, Xc, feat[r]);
                    Xa[r] = Xb[r]; Xb[r] = Xc;
                }
            }
            // tanh (MUFU pipe), then deg-5 Horner
            ull z[RPI];
            #pragma unroll
            for (int r = 0; r < RPI; ++r) {
                float lo, hi; upk2(feat[r], lo, hi);
                z[r] = pk2(tanh_fast(lo), tanh_fast(hi));
            }
            const ull q5 = pc_s[i][5][lane], q4 = pc_s[i][4][lane];
            const ull q3 = pc_s[i][3][lane], q2 = pc_s[i][2][lane];
            const ull q1 = pc_s[i][1][lane], q0 = pc_s[i][0][lane];
            #pragma unroll
            for (int r = 0; r < RPI; ++r) {
                ull t = fma2(q5, z[r], q4);
                t = fma2(t, z[r], q3);
                t = fma2(t, z[r], q2);
                t = fma2(t, z[r], q1);
                t = fma2(t, z[r], q0);
                acc[r] = add2(acc[r], t);
            }
        }

        // 4 independent 5-level warp reductions (they overlap)
        #pragma unroll
        for (int r = 0; r < RPI; ++r) {
            #pragma unroll
            for (int o = 16; o; o >>= 1)
                acc[r] = add2(acc[r], __shfl_xor_sync(0xffffffffu, acc[r], o));
        }

        if (lane == 0) {
            #pragma unroll
            for (int r = 0; r < RPI; ++r) {
                if ((RPI * g + r) < RP) {
                    float lo, hi; upk2(acc[r], lo, hi);
                    ((float2*)out)[RPI * g + r] = make_float2(lo, hi);
                }
            }
        }
    }
}

extern "C" void kernel_launch(void* const* d_in, const int* in_sizes, int n_in,
                              void* d_out, int out_size)
{
    const float* X  = (const float*)d_in[0];   // [B, 64] fp32
    const float* W  = (const float*)d_in[1];   // [64, 16] fp32
    const float* KC = (const float*)d_in[2];   // [1, 64, 6] fp32
    float* out = (float*)d_out;                // [B] fp32

    const int B  = in_sizes[0] / F;            // 65536
    const int RP = B / 2;

    qkan_kernel<<<NBLK, NTHR>>>(X, W, KC, out, RP);
}

// round 3
// speedup vs baseline: 1.5020x; 1.1328x over previous
#include <cuda_runtime.h>
#include <cstdint>

// QuantumKANRegressor: out[b] = sum_f sum_j kan[f,j] * T_j( tanh( sum_k w[f,k]*T_{k+1}(X[b,f]) / sum_k|w[f,k]| ) )
// B=65536, F=64, DEG=16 (T_1..T_16), KAN_DEG=5 (T_0..T_5)
//
// R3: RPI=2 (reg relief), 3 CTAs/SM, register prefetch of next group's X,
// folded 64-bit warp reduction, no inner predication.

typedef unsigned long long ull;

__device__ __forceinline__ ull pk2(float lo, float hi) {
    ull d; asm("mov.b64 %0, {%1, %2};" : "=l"(d) : "f"(lo), "f"(hi)); return d;
}
__device__ __forceinline__ void upk2(ull v, float& lo, float& hi) {
    asm("mov.b64 {%0, %1}, %2;" : "=f"(lo), "=f"(hi) : "l"(v));
}
__device__ __forceinline__ ull fma2(ull a, ull b, ull c) {
    ull d; asm("fma.rn.f32x2 %0, %1, %2, %3;" : "=l"(d) : "l"(a), "l"(b), "l"(c)); return d;
}
__device__ __forceinline__ ull add2(ull a, ull b) {
    ull d; asm("add.rn.f32x2 %0, %1, %2;" : "=l"(d) : "l"(a), "l"(b)); return d;
}
__device__ __forceinline__ ull mul2(ull a, ull b) {
    ull d; asm("mul.rn.f32x2 %0, %1, %2;" : "=l"(d) : "l"(a), "l"(b)); return d;
}
__device__ __forceinline__ float ex2f(float x) {
    float y; asm("ex2.approx.f32 %0, %1;" : "=f"(y) : "f"(x)); return y;
}
__device__ __forceinline__ float rcpf(float x) {
    float y; asm("rcp.approx.f32 %0, %1;" : "=f"(y) : "f"(x)); return y;
}
// tanh(f) = 1 - 2/(1 + exp(2f)); exp via ex2 (MUFU). ~1e-6 abs error on |f|<=1.
__device__ __forceinline__ float tanh_fast(float f) {
    float e = ex2f(f * 2.8853900817779268f);   // 2 * log2(e)
    float r = rcpf(e + 1.0f);
    return fmaf(-2.0f, r, 1.0f);
}

static constexpr int F    = 64;
static constexpr int DEG  = 16;
static constexpr int NBLK = 444;   // 3 CTAs/SM * 148 SMs
static constexpr int NTHR = 256;
static constexpr int RPI  = 2;     // row-pairs per warp-iteration (4 rows)

__global__ void __launch_bounds__(NTHR, 3)
qkan_kernel(const float* __restrict__ X,
            const float* __restrict__ W,    // [F, DEG]
            const float* __restrict__ KC,   // [1, F, 6]
            float* __restrict__ out,        // [B]
            int RP)                          // number of row-pairs = B/2
{
    // Parity-plane weight storage: plane i holds features f = 2*l + i at slot l.
    // Lane reads plane[i][j][lane] -> consecutive 8B addresses: conflict-free LDS.64.
    __shared__ ull wq_s[2][DEG][32];
    __shared__ ull pc_s[2][6][32];

    const int tid = threadIdx.x;

    // -------- per-block weight preprocessing (64 threads, once) --------
    if (tid < F) {
        const int f = tid;
        const int ip = f & 1;
        const int l  = f >> 1;
        float t[DEG];
        float den = 0.0f;
        #pragma unroll
        for (int k = 0; k < DEG; ++k) { t[k] = W[f * DEG + k]; den += fabsf(t[k]); }
        const float rd = 1.0f / den;
        // Sign-folded Chebyshev: X_k = s_k*T_k, s_k = -1 for k mod 4 in {2,3};
        // recurrence X_j = fma( (j odd ? +2x : -2x), X_{j-1}, X_{j-2} ).
        #pragma unroll
        for (int k = 0; k < DEG; ++k) {
            const int kk = k + 1;
            float v = t[k] * rd;
            if (kk & 2) v = -v;
            wq_s[ip][k][l] = pk2(v, v);
        }
        // KAN Chebyshev (deg 5) -> monomial Horner coefficients
        const float k0 = KC[f*6+0], k1 = KC[f*6+1], k2 = KC[f*6+2];
        const float k3 = KC[f*6+3], k4 = KC[f*6+4], k5 = KC[f*6+5];
        const float p0 = k0 - k2 + k4;
        const float p1 = k1 - 3.0f*k3 + 5.0f*k5;
        const float p2 = 2.0f*k2 - 8.0f*k4;
        const float p3 = 4.0f*k3 - 20.0f*k5;
        const float p4 = 8.0f*k4;
        const float p5 = 16.0f*k5;
        pc_s[ip][0][l] = pk2(p0, p0); pc_s[ip][1][l] = pk2(p1, p1);
        pc_s[ip][2][l] = pk2(p2, p2); pc_s[ip][3][l] = pk2(p3, p3);
        pc_s[ip][4][l] = pk2(p4, p4); pc_s[ip][5][l] = pk2(p5, p5);
    }
    __syncthreads();

    const ull ONE2  = 0x3F8000003F800000ull;   // (1.0f, 1.0f)
    const ull NEG22 = 0xC0000000C0000000ull;   // (-2.0f, -2.0f)

    const int lane = tid & 31;
    const int gw   = (blockIdx.x * NTHR + tid) >> 5;
    const int nW   = (gridDim.x * NTHR) >> 5;
    const int nG   = RP / RPI;                 // RP divisible by RPI (B % 4 == 0)

    // ---- prefetch first group ----
    int g = gw;
    float2 ca0, cb0, ca1, cb1;                 // current group's X (4 rows x 2 feats)
    if (g < nG) {
        const float2* base = (const float2*)X + (size_t)(4 * g) * 32 + lane;
        ca0 = __ldg(base + 0 * 32);
        cb0 = __ldg(base + 1 * 32);
        ca1 = __ldg(base + 2 * 32);
        cb1 = __ldg(base + 3 * 32);
    }

    while (g < nG) {
        const int gn = g + nW;
        // ---- issue next group's loads before computing current ----
        float2 na0, nb0, na1, nb1;
        if (gn < nG) {
            const float2* base = (const float2*)X + (size_t)(4 * gn) * 32 + lane;
            na0 = __ldg(base + 0 * 32);
            nb0 = __ldg(base + 1 * 32);
            na1 = __ldg(base + 2 * 32);
            nb1 = __ldg(base + 3 * 32);
        }

        ull acc0 = 0ull, acc1 = 0ull;
        #pragma unroll
        for (int i = 0; i < 2; ++i) {          // feature-parity phase
            const ull x0 = i ? pk2(ca0.y, cb0.y) : pk2(ca0.x, cb0.x);
            const ull x1 = i ? pk2(ca1.y, cb1.y) : pk2(ca1.x, cb1.x);
            const ull p2x0 = add2(x0, x0), p2x1 = add2(x1, x1);
            const ull m2x0 = mul2(x0, NEG22), m2x1 = mul2(x1, NEG22);
            ull Xa0 = x0, Xa1 = x1;
            ull Xb0 = fma2(m2x0, x0, ONE2);
            ull Xb1 = fma2(m2x1, x1, ONE2);
            const ull w0 = wq_s[i][0][lane];
            const ull w1 = wq_s[i][1][lane];
            ull f0 = mul2(w0, Xa0);
            ull f1 = mul2(w0, Xa1);
            f0 = fma2(w1, Xb0, f0);
            f1 = fma2(w1, Xb1, f1);
            #pragma unroll
            for (int j = 3; j <= DEG; ++j) {
                const ull w = wq_s[i][j - 1][lane];
                const ull Xc0 = fma2((j & 1) ? p2x0 : m2x0, Xb0, Xa0);
                const ull Xc1 = fma2((j & 1) ? p2x1 : m2x1, Xb1, Xa1);
                f0 = fma2(w, Xc0, f0);
                f1 = fma2(w, Xc1, f1);
                Xa0 = Xb0; Xb0 = Xc0;
                Xa1 = Xb1; Xb1 = Xc1;
            }
            // tanh (MUFU) then deg-5 Horner
            float l0, h0, l1, h1;
            upk2(f0, l0, h0); upk2(f1, l1, h1);
            const ull z0 = pk2(tanh_fast(l0), tanh_fast(h0));
            const ull z1 = pk2(tanh_fast(l1), tanh_fast(h1));
            const ull q5 = pc_s[i][5][lane], q4 = pc_s[i][4][lane];
            const ull q3 = pc_s[i][3][lane], q2 = pc_s[i][2][lane];
            const ull q1 = pc_s[i][1][lane], q0 = pc_s[i][0][lane];
            ull t0 = fma2(q5, z0, q4);
            ull t1 = fma2(q5, z1, q4);
            t0 = fma2(t0, z0, q3); t1 = fma2(t1, z1, q3);
            t0 = fma2(t0, z0, q2); t1 = fma2(t1, z1, q2);
            t0 = fma2(t0, z0, q1); t1 = fma2(t1, z1, q1);
            t0 = fma2(t0, z0, q0); t1 = fma2(t1, z1, q0);
            acc0 = add2(acc0, t0);
            acc1 = add2(acc1, t1);
        }

        // ---- folded warp reduction ----
        // Fold acc0/acc1 into one value at the offset-16 level:
        // lanes 0-15 carry acc0 partials, lanes 16-31 carry acc1 partials.
        {
            ull m = (lane & 16) ? acc1 : acc0;
            ull o = (lane & 16) ? acc0 : acc1;
            m = add2(m, __shfl_xor_sync(0xffffffffu, o, 16));
            #pragma unroll
            for (int off = 8; off; off >>= 1)
                m = add2(m, __shfl_xor_sync(0xffffffffu, m, off));
            if ((lane & 15) == 0) {
                float lo, hi; upk2(m, lo, hi);
                // lane 0 -> rows (4g, 4g+1); lane 16 -> rows (4g+2, 4g+3)
                ((float2*)out)[2 * g + (lane >> 4)] = make_float2(lo, hi);
            }
        }

        // ---- rotate buffers ----
        ca0 = na0; cb0 = nb0; ca1 = na1; cb1 = nb1;
        g = gn;
    }
}

extern "C" void kernel_launch(void* const* d_in, const int* in_sizes, int n_in,
                              void* d_out, int out_size)
{
    const float* X  = (const float*)d_in[0];   // [B, 64] fp32
    const float* W  = (const float*)d_in[1];   // [64, 16] fp32
    const float* KC = (const float*)d_in[2];   // [1, 64, 6] fp32
    float* out = (float*)d_out;                // [B] fp32

    const int B  = in_sizes[0] / F;            // 65536
    const int RP = B / 2;

    qkan_kernel<<<NBLK, NTHR>>>(X, W, KC, out, RP);
}